// round 2
// baseline (speedup 1.0000x reference)
#include <cuda_runtime.h>
#include <math.h>

#define D        512
#define KK       32
#define PP       528     // KK*(KK+1)/2
#define TN       16      // rows per block
#define PC       8       // p-chunk for V staging
#define NTHREADS 256

// floats: Zs(TN*D=8192) + Hs(TN*PP=8448) + ZUs(TN*KK=512) + Vs(PC*D=4096)
//         + kern(16) + pbuf(256)  = 21520 floats ; + gid (16 ints)
#define SMEM_BYTES ((21520 + 16) * 4)

// ---------------- device-global scratch (no allocations allowed) ------------
__device__ float g_Vt[PP * D];      // V transposed: Vt[p][d]
__device__ float g_change[D];
__device__ float g_xmuU[KK];
__device__ float g_xcU[KK];
__device__ unsigned char g_iu0[PP];
__device__ unsigned char g_iu1[PP];

// ---------------- setup: projections, change vector, triu table -------------
__global__ void setup_kernel(const float* __restrict__ U,
                             const float* __restrict__ zmu,
                             const float* __restrict__ xc) {
    __shared__ float s_diff[KK];
    int t = threadIdx.x;
    if (t < KK) {
        float a = 0.f, b = 0.f;
        for (int d = 0; d < D; ++d) {
            float u = U[d * KK + t];
            a = fmaf(zmu[d], u, a);
            b = fmaf(xc[d],  u, b);
        }
        g_xmuU[t] = a;
        g_xcU[t]  = b;
        s_diff[t] = b - a;
    }
    __syncthreads();
    for (int d = t; d < D; d += NTHREADS) {
        float s = 0.f;
        for (int j = 0; j < KK; ++j) s = fmaf(s_diff[j], U[d * KK + j], s);
        g_change[d] = xc[d] - zmu[d] - s;
    }
    if (t == 0) {
        int p = 0;
        for (int i = 0; i < KK; ++i)
            for (int j = i; j < KK; ++j) {
                g_iu0[p] = (unsigned char)i;
                g_iu1[p] = (unsigned char)j;
                ++p;
            }
    }
}

// ---------------- V transpose: Vt[p][d] = V[d][p] ---------------------------
__global__ void transpose_kernel(const float* __restrict__ V) {
    int idx = blockIdx.x * blockDim.x + threadIdx.x;
    if (idx < PP * D) {
        int p = idx >> 9;          // idx / 512
        int d = idx & (D - 1);
        g_Vt[idx] = V[d * PP + p];
    }
}

// ---------------- main fused kernel -----------------------------------------
__global__ __launch_bounds__(NTHREADS, 2)
void glayer_main(const float* __restrict__ Z_all,
                 const float* __restrict__ U,
                 const float* __restrict__ zmu,
                 const int*   __restrict__ choice,
                 float*       __restrict__ out,
                 int Nc) {
    extern __shared__ float sm[];
    float* Zs   = sm;                    // TN*D
    float* Hs   = Zs  + TN * D;          // TN*PP
    float* ZUs  = Hs  + TN * PP;         // TN*KK
    float* Vs   = ZUs + TN * KK;         // PC*D
    float* kern = Vs  + PC * D;          // TN
    float* pbuf = kern + TN;             // NTHREADS
    int*   gid  = (int*)(pbuf + NTHREADS); // TN

    const int tid = threadIdx.x;
    const int n0  = blockIdx.x * TN;

    if (tid < TN) {
        int n = n0 + tid;
        gid[tid] = (n < Nc) ? choice[n] : -1;
    }
    __syncthreads();

    // ---- gather Z tile (coalesced within rows) ----
    for (int e = tid; e < TN * D; e += NTHREADS) {
        int r = e >> 9;            // e / 512
        int d = e & (D - 1);
        int g = gid[r];
        Zs[e] = (g >= 0) ? Z_all[(size_t)g * D + d] : 0.f;
    }
    __syncthreads();

    // ---- ZU = Z @ U : 512 entries, 2 per thread ----
    for (int e = tid; e < TN * KK; e += NTHREADS) {
        int r = e >> 5;
        int j = e & (KK - 1);
        const float* zr = Zs + r * D;
        float a0 = 0.f, a1 = 0.f, a2 = 0.f, a3 = 0.f;
        #pragma unroll 4
        for (int d = 0; d < D; d += 4) {
            a0 = fmaf(zr[d + 0], U[(d + 0) * KK + j], a0);
            a1 = fmaf(zr[d + 1], U[(d + 1) * KK + j], a1);
            a2 = fmaf(zr[d + 2], U[(d + 2) * KK + j], a2);
            a3 = fmaf(zr[d + 3], U[(d + 3) * KK + j], a3);
        }
        ZUs[e] = (a0 + a1) + (a2 + a3);
    }

    // ---- Z_norm2 partials: 16 threads per row ----
    {
        int r = tid >> 4;
        int l = tid & 15;
        const float* zr = Zs + r * D;
        float s = 0.f;
        for (int d = l; d < D; d += 16) {
            float v = zr[d] - zmu[d];
            s = fmaf(v, v, s);
        }
        pbuf[tid] = s;
    }
    __syncthreads();

    // ---- warp 0 lanes 0..15: norms + secant root solve -> kern[r] ----
    //      warps 1..7: build H tile (independent of secant)
    if (tid < TN) {
        float zn = 0.f;
        for (int k = 0; k < 16; ++k) zn += pbuf[tid * 16 + k];
        float un = 0.f;
        for (int j = 0; j < KK; ++j) {
            float v = ZUs[tid * KK + j] - g_xmuU[j];
            un = fmaf(v, v, un);
        }
        float C = zn - un;                    // ZUperp_norm2
        float E = expf(-0.01f * un);          // exp(-gamma*ZU_norm2)
        float x_m2 = C * 0.999f;              // GUESS_RATIO
        float x_m1 = C;
        bool  done = false;
        for (int it = 0; it < 100; ++it) {
            if (done) break;
            float t1 = 1.f - E * expf(-0.01f * x_m1);
            float f1 = t1 * t1 * x_m1 - C;
            float t2 = 1.f - E * expf(-0.01f * x_m2);
            float f2 = t2 * t2 * x_m2 - C;
            float fd = f1 - f2;
            if (fabsf(fd) < 1e-6f) fd = (fd >= 0.f) ? 1e-6f : -1e-6f;
            float x = x_m1 - f1 * (x_m1 - x_m2) / fd;
            float step = fabsf(x - x_m1);
            x_m2 = x_m1;
            x_m1 = x;
            done = (step < 1e-6f);
        }
        kern[tid] = expf(-0.01f * (un + x_m1));   // alpha = 1
    } else if (tid >= 32) {
        for (int e = tid - 32; e < TN * PP; e += (NTHREADS - 32)) {
            int r = e / PP;
            int p = e - r * PP;
            int i0 = g_iu0[p], i1 = g_iu1[p];
            float ci = ZUs[r * KK + i0] - g_xcU[i0];
            float cj = ZUs[r * KK + i1] - g_xcU[i1];
            Hs[e] = ci * cj;
        }
    }
    __syncthreads();

    // ---- GEMM: acc[4][8] per thread;  rows rg*4+i, cols cg+64k ----
    const int rg = tid >> 6;    // 0..3
    const int cg = tid & 63;    // 0..63
    float acc[4][8];
    #pragma unroll
    for (int i = 0; i < 4; ++i)
        #pragma unroll
        for (int k = 0; k < 8; ++k) acc[i][k] = 0.f;

    for (int p0 = 0; p0 < PP; p0 += PC) {
        #pragma unroll
        for (int k = 0; k < (PC * D) / NTHREADS; ++k) {   // 16 staging loads
            int idx = tid + k * NTHREADS;
            Vs[idx] = g_Vt[(p0 + (idx >> 9)) * D + (idx & (D - 1))];
        }
        __syncthreads();
        #pragma unroll
        for (int pc = 0; pc < PC; ++pc) {
            float h0 = Hs[(rg * 4 + 0) * PP + p0 + pc];
            float h1 = Hs[(rg * 4 + 1) * PP + p0 + pc];
            float h2 = Hs[(rg * 4 + 2) * PP + p0 + pc];
            float h3 = Hs[(rg * 4 + 3) * PP + p0 + pc];
            #pragma unroll
            for (int k = 0; k < 8; ++k) {
                float v = Vs[pc * D + cg + 64 * k];
                acc[0][k] = fmaf(h0, v, acc[0][k]);
                acc[1][k] = fmaf(h1, v, acc[1][k]);
                acc[2][k] = fmaf(h2, v, acc[2][k]);
                acc[3][k] = fmaf(h3, v, acc[3][k]);
            }
        }
        __syncthreads();
    }

    // ---- epilogue: out[g] = Z + kern*(change + H@Vt) ----
    #pragma unroll
    for (int i = 0; i < 4; ++i) {
        int r = rg * 4 + i;
        int g = gid[r];
        if (g < 0) continue;
        float kr = kern[r];
        #pragma unroll
        for (int k = 0; k < 8; ++k) {
            int d = cg + 64 * k;
            out[(size_t)g * D + d] =
                Zs[r * D + d] + kr * (g_change[d] + acc[i][k]);
        }
    }
}

// ---------------- launch ----------------------------------------------------
extern "C" void kernel_launch(void* const* d_in, const int* in_sizes, int n_in,
                              void* d_out, int out_size) {
    const float* Z_all  = (const float*)d_in[0];
    const float* U      = (const float*)d_in[1];
    const float* V      = (const float*)d_in[2];
    const float* zmu    = (const float*)d_in[3];
    const float* xc     = (const float*)d_in[4];
    const int*   choice = (const int*)  d_in[5];
    float*       out    = (float*)d_out;
    const int Nc = in_sizes[5];

    // default output = (renormalized) Z_all; Z_NORM=1, Z_MU=0 -> plain copy
    cudaMemcpyAsync(d_out, Z_all, (size_t)in_sizes[0] * sizeof(float),
                    cudaMemcpyDeviceToDevice, 0);

    setup_kernel<<<1, NTHREADS>>>(U, zmu, xc);
    transpose_kernel<<<(PP * D + 255) / 256, 256>>>(V);

    cudaFuncSetAttribute(glayer_main,
                         cudaFuncAttributeMaxDynamicSharedMemorySize,
                         SMEM_BYTES);
    int nblocks = (Nc + TN - 1) / TN;
    glayer_main<<<nblocks, NTHREADS, SMEM_BYTES>>>(Z_all, U, zmu, choice, out, Nc);
}

// round 4
// speedup vs baseline: 5.8967x; 5.8967x over previous
#include <cuda_runtime.h>
#include <cuda_bf16.h>
#include <math.h>
#include <stdint.h>

// ===================== problem constants =====================
#define D        512
#define KK       32
#define PP       528               // KK*(KK+1)/2
#define MROWS    128               // rows per CTA
#define KPAD     544               // PP padded to 17 chunks of 32
#define KCH      32                // k-chunk
#define NCHUNK   17
#define NTHREADS 256

// ===================== smem strides (bytes; /16 odd => ldmatrix conflict-free)
#define H_STRIDE 1104              // >= 544*2
#define Z_STRIDE 1040              // >= 512*2
#define V_STRIDE 528               // >= 264*2 (256 n + pad)
#define U_STRIDE 80                // >= 40*2  (32 n + pad)

// ===================== smem offsets (bytes) ==================
#define SM_GID   0                 // 128 int
#define SM_KERN  512               // 128 f
#define SM_PBUF  1024              // 256 f
#define SM_CHG   2048              // 512 f
#define SM_ZMU   4096              // 512 f
#define SM_COORD 6144              // 128*33 f = 16896
#define SM_R2    23040             // U (40960) / V chunk (16896)
#define SM_R1    64000             // Zbf (133120) / H (141312)
#define SM_TOTAL 205312

#define VCHUNK_BYTES (KCH * V_STRIDE)      // 16896
#define VCHUNK_U4    (VCHUNK_BYTES / 16)   // 1056

// ===================== device globals ========================
__device__ float g_change[D];
__device__ float g_xcU[KK];
__device__ float g_dU[KK];                 // xcU - xmuU
__device__ unsigned short g_iup[PP];       // i0 | (i1<<8)
__device__ __align__(16) unsigned char g_Ubf[512 * U_STRIDE];          // 40KB
__device__ __align__(16) unsigned char g_Vbf[34 * VCHUNK_BYTES];       // 561KB

// ===================== helpers ===============================
__device__ __forceinline__ uint32_t smem_u32(const void* p) {
    uint32_t a;
    asm("{ .reg .u64 t; cvta.to.shared.u64 t, %1; cvt.u32.u64 %0, t; }" : "=r"(a) : "l"(p));
    return a;
}
__device__ __forceinline__ void ldsm4(uint32_t* r, uint32_t a) {
    asm volatile("ldmatrix.sync.aligned.m8n8.x4.shared.b16 {%0,%1,%2,%3}, [%4];"
                 : "=r"(r[0]), "=r"(r[1]), "=r"(r[2]), "=r"(r[3]) : "r"(a));
}
__device__ __forceinline__ void ldsm4t(uint32_t* r, uint32_t a) {
    asm volatile("ldmatrix.sync.aligned.m8n8.x4.trans.shared.b16 {%0,%1,%2,%3}, [%4];"
                 : "=r"(r[0]), "=r"(r[1]), "=r"(r[2]), "=r"(r[3]) : "r"(a));
}
__device__ __forceinline__ void mma16816(float* c, const uint32_t* a, const uint32_t* b) {
    asm volatile("mma.sync.aligned.m16n8k16.row.col.f32.bf16.bf16.f32 "
                 "{%0,%1,%2,%3}, {%4,%5,%6,%7}, {%8,%9}, {%0,%1,%2,%3};"
                 : "+f"(c[0]), "+f"(c[1]), "+f"(c[2]), "+f"(c[3])
                 : "r"(a[0]), "r"(a[1]), "r"(a[2]), "r"(a[3]), "r"(b[0]), "r"(b[1]));
}

// ===================== prep kernels ==========================
__global__ void setup_kernel(const float* __restrict__ U,
                             const float* __restrict__ zmu,
                             const float* __restrict__ xc) {
    __shared__ float pa[256], pb[256], sdiff[KK];
    int t = threadIdx.x;
    {
        int j = t & 31, seg = t >> 5;
        float a = 0.f, b = 0.f;
        for (int i = 0; i < 64; ++i) {
            int d = seg * 64 + i;
            float u = U[d * KK + j];
            a = fmaf(zmu[d], u, a);
            b = fmaf(xc[d],  u, b);
        }
        pa[t] = a; pb[t] = b;
    }
    __syncthreads();
    if (t < KK) {
        float sa = 0.f, sb = 0.f;
        for (int s = 0; s < 8; ++s) { sa += pa[s * 32 + t]; sb += pb[s * 32 + t]; }
        g_xcU[t] = sb;
        g_dU[t]  = sb - sa;
        sdiff[t] = sb - sa;
    }
    __syncthreads();
    for (int d = t; d < D; d += 256) {
        float s = 0.f;
        for (int j = 0; j < KK; ++j) s = fmaf(sdiff[j], U[d * KK + j], s);
        g_change[d] = xc[d] - zmu[d] - s;
    }
    if (t == 0) {
        int p = 0;
        for (int i = 0; i < KK; ++i)
            for (int j = i; j < KK; ++j) {
                g_iup[p] = (unsigned short)(i | (j << 8));
                ++p;
            }
    }
    // U -> bf16 k-major [512][40] (pad cols zero)
    for (int e = t; e < 512 * 40; e += 256) {
        int k = e / 40, n = e - k * 40;
        float v = (n < KK) ? U[k * KK + n] : 0.f;
        *(__nv_bfloat16*)(g_Ubf + k * U_STRIDE + n * 2) = __float2bfloat16(v);
    }
}

__global__ void vprep_kernel(const float* __restrict__ V) {
    int idx = blockIdx.x * blockDim.x + threadIdx.x;
    if (idx >= 34 * KCH * 264) return;
    int t = idx / (KCH * 264);
    int rem = idx - t * (KCH * 264);
    int k = rem / 264, n = rem - k * 264;
    int np = t / NCHUNK, c = t - np * NCHUNK;
    int gk = c * KCH + k;            // 0..543
    int gn = np * 256 + n;           // col in D
    float v = (gk < PP && n < 256) ? V[gn * PP + gk] : 0.f;
    *(__nv_bfloat16*)(g_Vbf + (size_t)t * VCHUNK_BYTES + k * V_STRIDE + n * 2) =
        __float2bfloat16(v);
}

// ===================== main kernel ===========================
__global__ __launch_bounds__(NTHREADS, 1)
void glayer_main(const float* __restrict__ Z_all,
                 const float* __restrict__ zmu,
                 const int*   __restrict__ choice,
                 float*       __restrict__ out,
                 int Nc) {
    extern __shared__ __align__(16) char sm[];
    const uint32_t smb = smem_u32(sm);

    int*   gid    = (int*)(sm + SM_GID);
    float* kern   = (float*)(sm + SM_KERN);
    float* pbuf   = (float*)(sm + SM_PBUF);
    float* chg    = (float*)(sm + SM_CHG);
    float* zmus   = (float*)(sm + SM_ZMU);
    float* coords = (float*)(sm + SM_COORD);

    const int tid = threadIdx.x;
    const int wid = tid >> 5;
    const int lid = tid & 31;

    if (tid < MROWS) {
        int n = blockIdx.x * MROWS + tid;
        gid[tid] = (n < Nc) ? choice[n] : -1;
    }
    for (int i = tid; i < D; i += NTHREADS) { zmus[i] = zmu[i]; chg[i] = g_change[i]; }
    {   // stage U tile (40960B = 2560 uint4)
        const uint4* s = (const uint4*)g_Ubf;
        uint4* d = (uint4*)(sm + SM_R2);
        #pragma unroll
        for (int i = 0; i < 10; ++i) d[tid + i * 256] = s[tid + i * 256];
    }
    __syncthreads();

    // ---- gather Z -> bf16 Zbf[128][520] + zn partials ----
    {
        int r = tid >> 1, hh = tid & 1;
        int g = gid[r];
        const float4* zr = (const float4*)(Z_all + (size_t)(g < 0 ? 0 : g) * D) + hh * 64;
        char* zrow = sm + SM_R1 + r * Z_STRIDE + hh * 512;
        float acc = 0.f;
        #pragma unroll 4
        for (int i = 0; i < 64; ++i) {
            float4 z = make_float4(0.f, 0.f, 0.f, 0.f);
            if (g >= 0) z = zr[i];
            int d0 = hh * 256 + i * 4;
            float a0 = z.x - zmus[d0], a1 = z.y - zmus[d0 + 1];
            float a2 = z.z - zmus[d0 + 2], a3 = z.w - zmus[d0 + 3];
            acc = fmaf(a0, a0, fmaf(a1, a1, fmaf(a2, a2, fmaf(a3, a3, acc))));
            __nv_bfloat162 p0 = __floats2bfloat162_rn(z.x, z.y);
            __nv_bfloat162 p1 = __floats2bfloat162_rn(z.z, z.w);
            *(uint32_t*)(zrow + i * 8)     = *(uint32_t*)&p0;
            *(uint32_t*)(zrow + i * 8 + 4) = *(uint32_t*)&p1;
        }
        pbuf[tid] = acc;
    }
    __syncthreads();

    // ---- ZU = Z @ U via mma: warp w owns rows w*16..w*16+15 ----
    {
        float zu[4][4];
        #pragma unroll
        for (int i = 0; i < 4; ++i)
            #pragma unroll
            for (int j = 0; j < 4; ++j) zu[i][j] = 0.f;

        uint32_t zbase = smb + SM_R1 + (uint32_t)(wid * 16 + (lid & 15)) * Z_STRIDE;
        uint32_t ubase = smb + SM_R2 +
                         (uint32_t)((lid & 7) + 8 * ((lid >> 3) & 1)) * U_STRIDE +
                         (uint32_t)(8 * (lid >> 4)) * 2;
        uint32_t kh = (uint32_t)(8 * (lid >> 4)) * 2;
        #pragma unroll 4
        for (int ks = 0; ks < 32; ++ks) {
            uint32_t a[4], b0[4], b1[4];
            ldsm4(a, zbase + (uint32_t)(ks * 32) + kh);
            ldsm4t(b0, ubase + (uint32_t)(ks * 16) * U_STRIDE);
            ldsm4t(b1, ubase + (uint32_t)(ks * 16) * U_STRIDE + 32);
            mma16816(zu[0], a, b0);
            mma16816(zu[1], a, b0 + 2);
            mma16816(zu[2], a, b1);
            mma16816(zu[3], a, b1 + 2);
        }
        int r0 = wid * 16 + (lid >> 2);
        int c0 = (lid & 3) * 2;
        #pragma unroll
        for (int nt = 0; nt < 4; ++nt) {
            int c = nt * 8 + c0;
            coords[r0 * 33 + c]           = zu[nt][0] - g_xcU[c];
            coords[r0 * 33 + c + 1]       = zu[nt][1] - g_xcU[c + 1];
            coords[(r0 + 8) * 33 + c]     = zu[nt][2] - g_xcU[c];
            coords[(r0 + 8) * 33 + c + 1] = zu[nt][3] - g_xcU[c + 1];
        }
    }
    __syncthreads();

    // ---- secant (threads 0..127) ----
    if (tid < MROWS) {
        const float* cr = coords + tid * 33;
        float un = 0.f;
        #pragma unroll
        for (int j = 0; j < KK; ++j) {
            float v = cr[j] + g_dU[j];
            un = fmaf(v, v, un);
        }
        float zn = pbuf[2 * tid] + pbuf[2 * tid + 1];
        float C = zn - un;
        float E = expf(-0.01f * un);
        float x_m2 = C * 0.999f;
        float x_m1 = C;
        bool done = false;
        for (int it = 0; it < 100; ++it) {
            if (done) break;
            float t1 = 1.f - E * expf(-0.01f * x_m1);
            float f1 = t1 * t1 * x_m1 - C;
            float t2 = 1.f - E * expf(-0.01f * x_m2);
            float f2 = t2 * t2 * x_m2 - C;
            float fd = f1 - f2;
            if (fabsf(fd) < 1e-6f) fd = (fd >= 0.f) ? 1e-6f : -1e-6f;
            float x = x_m1 - f1 * (x_m1 - x_m2) / fd;
            float step = fabsf(x - x_m1);
            x_m2 = x_m1;
            x_m1 = x;
            done = (step < 1e-6f);
        }
        kern[tid] = expf(-0.01f * (un + x_m1));
    }

    // ---- build H[128][544] bf16 (overwrites Zbf; ZU mma is done) ----
    {
        int m = tid >> 1, hh = tid & 1;
        const float* cr = coords + m * 33;
        char* hrow = sm + SM_R1 + m * H_STRIDE;
        int pend = hh * 272 + 272;
        for (int p = hh * 272; p < pend; ++p) {
            float h = 0.f;
            if (p < PP) {
                unsigned pr = g_iup[p];
                h = cr[pr & 31] * cr[(pr >> 8) & 31];
            }
            *(__nv_bfloat16*)(hrow + p * 2) = __float2bfloat16(h);
        }
    }
    __syncthreads();

    // ---- main GEMM: H(128x544) @ V -> 2 passes of N=256 ----
    const int mg = (wid >> 2) * 64;     // m-group base row
    const int ng = (wid & 3) * 64;      // n-group base col (within pass)
    const uint32_t hbase = smb + SM_R1 + (uint32_t)(mg + (lid & 15)) * H_STRIDE +
                           (uint32_t)(8 * (lid >> 4)) * 2;
    const uint32_t vbase = smb + SM_R2 +
                           (uint32_t)((lid & 7) + 8 * ((lid >> 3) & 1)) * V_STRIDE +
                           (uint32_t)(ng + 8 * (lid >> 4)) * 2;
    uint4* vdst = (uint4*)(sm + SM_R2);

    for (int np = 0; np < 2; ++np) {
        float acc[4][8][4];
        #pragma unroll
        for (int i = 0; i < 4; ++i)
            #pragma unroll
            for (int j = 0; j < 8; ++j)
                #pragma unroll
                for (int q = 0; q < 4; ++q) acc[i][j][q] = 0.f;

        {   // stage chunk 0
            const uint4* src = (const uint4*)(g_Vbf + (size_t)(np * NCHUNK) * VCHUNK_BYTES);
            #pragma unroll
            for (int i = 0; i < 4; ++i) vdst[tid + i * 256] = src[tid + i * 256];
            if (tid < 32) vdst[tid + 1024] = src[tid + 1024];
        }
        __syncthreads();

        for (int c = 0; c < NCHUNK; ++c) {
            // prefetch next chunk into registers
            uint4 t4[5];
            const bool have = (c + 1 < NCHUNK);
            if (have) {
                const uint4* nsrc =
                    (const uint4*)(g_Vbf + (size_t)(np * NCHUNK + c + 1) * VCHUNK_BYTES);
                #pragma unroll
                for (int i = 0; i < 4; ++i) t4[i] = nsrc[tid + i * 256];
                if (tid < 32) t4[4] = nsrc[tid + 1024];
            }
            // compute chunk c: 2 k-steps
            #pragma unroll
            for (int ks = 0; ks < 2; ++ks) {
                uint32_t a[4][4], b[4][4];
                uint32_t kb = (uint32_t)((c * KCH + ks * 16) * 2);
                #pragma unroll
                for (int mt = 0; mt < 4; ++mt)
                    ldsm4(a[mt], hbase + (uint32_t)(mt * 16) * H_STRIDE + kb);
                uint32_t vk = vbase + (uint32_t)(ks * 16) * V_STRIDE;
                #pragma unroll
                for (int q = 0; q < 4; ++q)
                    ldsm4t(b[q], vk + (uint32_t)(q * 32));
                #pragma unroll
                for (int mt = 0; mt < 4; ++mt)
                    #pragma unroll
                    for (int q = 0; q < 4; ++q) {
                        mma16816(acc[mt][2 * q],     a[mt], b[q]);
                        mma16816(acc[mt][2 * q + 1], a[mt], b[q] + 2);
                    }
            }
            __syncthreads();
            if (have) {
                #pragma unroll
                for (int i = 0; i < 4; ++i) vdst[tid + i * 256] = t4[i];
                if (tid < 32) vdst[tid + 1024] = t4[4];
            }
            __syncthreads();
        }

        // ---- epilogue for this n-half ----
        {
            int r0 = mg + (lid >> 2);
            int c0 = np * 256 + ng + (lid & 3) * 2;
            #pragma unroll
            for (int mt = 0; mt < 4; ++mt) {
                int rA = r0 + mt * 16, rB = rA + 8;
                int gA = gid[rA], gB = gid[rB];
                float kA = kern[rA], kB = kern[rB];
                #pragma unroll
                for (int nt = 0; nt < 8; ++nt) {
                    int col = c0 + nt * 8;
                    float ca = chg[col], cb = chg[col + 1];
                    if (gA >= 0) {
                        float2 z = *(const float2*)(Z_all + (size_t)gA * D + col);
                        float2 o;
                        o.x = z.x + kA * (ca + acc[mt][nt][0]);
                        o.y = z.y + kA * (cb + acc[mt][nt][1]);
                        *(float2*)(out + (size_t)gA * D + col) = o;
                    }
                    if (gB >= 0) {
                        float2 z = *(const float2*)(Z_all + (size_t)gB * D + col);
                        float2 o;
                        o.x = z.x + kB * (ca + acc[mt][nt][2]);
                        o.y = z.y + kB * (cb + acc[mt][nt][3]);
                        *(float2*)(out + (size_t)gB * D + col) = o;
                    }
                }
            }
        }
        if (np == 0) __syncthreads();   // before restaging V for pass 2
    }
}

// ===================== launch ================================
extern "C" void kernel_launch(void* const* d_in, const int* in_sizes, int n_in,
                              void* d_out, int out_size) {
    const float* Z_all  = (const float*)d_in[0];
    const float* U      = (const float*)d_in[1];
    const float* V      = (const float*)d_in[2];
    const float* zmu    = (const float*)d_in[3];
    const float* xc     = (const float*)d_in[4];
    const int*   choice = (const int*)  d_in[5];
    float*       out    = (float*)d_out;
    const int Nc = in_sizes[5];

    // main kernel writes every chosen row; only pre-copy if choice can't cover
    if ((size_t)Nc * D != (size_t)in_sizes[0]) {
        cudaMemcpyAsync(d_out, Z_all, (size_t)in_sizes[0] * sizeof(float),
                        cudaMemcpyDeviceToDevice, 0);
    }

    setup_kernel<<<1, 256>>>(U, zmu, xc);
    vprep_kernel<<<(34 * KCH * 264 + 255) / 256, 256>>>(V);

    cudaFuncSetAttribute(glayer_main,
                         cudaFuncAttributeMaxDynamicSharedMemorySize, SM_TOTAL);
    int nblocks = (Nc + MROWS - 1) / MROWS;
    glayer_main<<<nblocks, NTHREADS, SM_TOTAL>>>(Z_all, zmu, choice, out, Nc);
}

// round 5
// speedup vs baseline: 6.0826x; 1.0315x over previous
#include <cuda_runtime.h>
#include <cuda_bf16.h>
#include <cuda_fp8.h>
#include <math.h>
#include <stdint.h>

// ===================== problem constants =====================
#define D        512
#define KK       32
#define PP       528               // KK*(KK+1)/2
#define MROWS    128               // rows per CTA
#define KCH      64                // fp8 k-chunk (2 mma k-steps of 32)
#define NCHUNK   9                 // 528 padded to 576
#define NTHREADS 256

// ===================== smem strides (bytes) ==================
#define H_STRIDE 592               // 576 fp8 + pad; /16 = 37 odd
#define Z_STRIDE 1040              // 512 bf16 + pad; /16 = 65 odd
#define V_STRIDE 80                // 64 fp8 + pad;  /16 = 5 odd
#define U_STRIDE 80                // 40 bf16;       /16 = 5 odd
#define VCHUNK_BYTES (256 * V_STRIDE)   // 20480

// ===================== smem offsets (bytes) ==================
#define SM_GID   0                 // 128 int
#define SM_KERN  512               // 128 f
#define SM_PBUF  1024              // 256 f
#define SM_CHG   2048              // 512 f
#define SM_ZMU   4096              // 512 f
#define SM_LUT   6144              // 544 ushort (1088B)
#define SM_COORD 7232              // 128*33 f = 16896
#define SM_R2    24192             // 40960: U tile / V double buffer (2x20480)
#define SM_R1    65152             // 133120: Zbf / H
#define SM_TOTAL 198272

// ===================== device globals ========================
__device__ float g_change[D];
__device__ float g_xcU[KK];
__device__ float g_dU[KK];
__device__ __align__(16) unsigned short g_iup[544];              // i0 | (i1<<8)
__device__ __align__(16) unsigned char g_Ubf[512 * U_STRIDE];    // 40KB bf16
__device__ __align__(16) unsigned char g_V8[18 * VCHUNK_BYTES];  // 360KB fp8 (x256)

// ===================== helpers ===============================
__device__ __forceinline__ uint32_t smem_u32(const void* p) {
    uint32_t a;
    asm("{ .reg .u64 t; cvta.to.shared.u64 t, %1; cvt.u32.u64 %0, t; }" : "=r"(a) : "l"(p));
    return a;
}
__device__ __forceinline__ void ldsm4(uint32_t* r, uint32_t a) {
    asm volatile("ldmatrix.sync.aligned.m8n8.x4.shared.b16 {%0,%1,%2,%3}, [%4];"
                 : "=r"(r[0]), "=r"(r[1]), "=r"(r[2]), "=r"(r[3]) : "r"(a));
}
__device__ __forceinline__ void ldsm4t(uint32_t* r, uint32_t a) {
    asm volatile("ldmatrix.sync.aligned.m8n8.x4.trans.shared.b16 {%0,%1,%2,%3}, [%4];"
                 : "=r"(r[0]), "=r"(r[1]), "=r"(r[2]), "=r"(r[3]) : "r"(a));
}
__device__ __forceinline__ void mma16816(float* c, const uint32_t* a, const uint32_t* b) {
    asm volatile("mma.sync.aligned.m16n8k16.row.col.f32.bf16.bf16.f32 "
                 "{%0,%1,%2,%3}, {%4,%5,%6,%7}, {%8,%9}, {%0,%1,%2,%3};"
                 : "+f"(c[0]), "+f"(c[1]), "+f"(c[2]), "+f"(c[3])
                 : "r"(a[0]), "r"(a[1]), "r"(a[2]), "r"(a[3]), "r"(b[0]), "r"(b[1]));
}
__device__ __forceinline__ void mma8(float* c, const uint32_t* a, uint32_t b0, uint32_t b1) {
    asm volatile("mma.sync.aligned.m16n8k32.row.col.f32.e4m3.e4m3.f32 "
                 "{%0,%1,%2,%3}, {%4,%5,%6,%7}, {%8,%9}, {%0,%1,%2,%3};"
                 : "+f"(c[0]), "+f"(c[1]), "+f"(c[2]), "+f"(c[3])
                 : "r"(a[0]), "r"(a[1]), "r"(a[2]), "r"(a[3]), "r"(b0), "r"(b1));
}
// pack 4 floats -> 4 e4m3 bytes (byte0=f0 .. byte3=f3)
__device__ __forceinline__ uint32_t pack4_e4m3(float f0, float f1, float f2, float f3) {
    uint32_t r;
    asm("{\n\t.reg .b16 lo, hi;\n\t"
        "cvt.rn.satfinite.e4m3x2.f32 lo, %2, %1;\n\t"
        "cvt.rn.satfinite.e4m3x2.f32 hi, %4, %3;\n\t"
        "mov.b32 %0, {lo, hi};\n\t}"
        : "=r"(r) : "f"(f0), "f"(f1), "f"(f2), "f"(f3));
    return r;
}

// ===================== prep kernel (one launch) ==============
// blocks 0..287: V -> fp8*256 tiled [18 chunks][256 n][64 k]
// blocks 288..367: U -> bf16 [512][40]
// block  368: consts (xcU, dU, change, iup)
__global__ void prep_kernel(const float* __restrict__ U,
                            const float* __restrict__ V,
                            const float* __restrict__ zmu,
                            const float* __restrict__ xc) {
    int b = blockIdx.x, t = threadIdx.x;
    if (b < 288) {
        int g = b * 256 + t;                  // group of 4 fp8
        int chunk = g >> 12;                  // 0..17
        int rem = g & 4095;
        int n = rem >> 4;
        int k4 = (rem & 15) << 2;
        int np = chunk / NCHUNK, c = chunk - np * NCHUNK;
        int gk = c * KCH + k4;
        int gn = np * 256 + n;
        float4 v = make_float4(0.f, 0.f, 0.f, 0.f);
        if (gk < PP) v = *(const float4*)(V + (size_t)gn * PP + gk);
        uint32_t w = pack4_e4m3(v.x * 256.f, v.y * 256.f, v.z * 256.f, v.w * 256.f);
        *(uint32_t*)(g_V8 + (size_t)chunk * VCHUNK_BYTES + n * V_STRIDE + k4) = w;
        return;
    }
    if (b < 368) {
        int e = (b - 288) * 256 + t;          // 0..20479
        int k = e / 40, n = e - k * 40;
        float v = (n < KK) ? U[k * KK + n] : 0.f;
        *(__nv_bfloat16*)(g_Ubf + k * U_STRIDE + n * 2) = __float2bfloat16(v);
        return;
    }
    // ---- consts block ----
    __shared__ float pa[256], pb[256], sdiff[KK];
    {
        int j = t & 31, seg = t >> 5;
        float a = 0.f, bb = 0.f;
        for (int i = 0; i < 64; ++i) {
            int d = seg * 64 + i;
            float u = U[d * KK + j];
            a = fmaf(zmu[d], u, a);
            bb = fmaf(xc[d], u, bb);
        }
        pa[t] = a; pb[t] = bb;
    }
    __syncthreads();
    if (t < KK) {
        float sa = 0.f, sb = 0.f;
        for (int s = 0; s < 8; ++s) { sa += pa[s * 32 + t]; sb += pb[s * 32 + t]; }
        g_xcU[t] = sb;
        g_dU[t]  = sb - sa;
        sdiff[t] = sb - sa;
    }
    __syncthreads();
    for (int d = t; d < D; d += 256) {
        float s = 0.f;
        for (int j = 0; j < KK; ++j) s = fmaf(sdiff[j], U[d * KK + j], s);
        g_change[d] = xc[d] - zmu[d] - s;
    }
    if (t == 0) {
        int p = 0;
        for (int i = 0; i < KK; ++i)
            for (int j = i; j < KK; ++j) {
                g_iup[p] = (unsigned short)(i | (j << 8));
                ++p;
            }
        for (; p < 544; ++p) g_iup[p] = 0;
    }
}

// ===================== main kernel ===========================
__global__ __launch_bounds__(NTHREADS, 1)
void glayer_main(const float* __restrict__ Z_all,
                 const float* __restrict__ zmu,
                 const int*   __restrict__ choice,
                 float*       __restrict__ out,
                 int Nc) {
    extern __shared__ __align__(16) char sm[];
    const uint32_t smb = smem_u32(sm);

    int*   gid    = (int*)(sm + SM_GID);
    float* kern   = (float*)(sm + SM_KERN);
    float* pbuf   = (float*)(sm + SM_PBUF);
    float* chg    = (float*)(sm + SM_CHG);
    float* zmus   = (float*)(sm + SM_ZMU);
    float* coords = (float*)(sm + SM_COORD);

    const int tid = threadIdx.x;
    const int wid = tid >> 5;
    const int lid = tid & 31;

    if (tid < MROWS) {
        int n = blockIdx.x * MROWS + tid;
        gid[tid] = (n < Nc) ? choice[n] : -1;
    }
    for (int i = tid; i < D; i += NTHREADS) { zmus[i] = zmu[i]; chg[i] = g_change[i]; }
    if (tid < 136) ((uint2*)(sm + SM_LUT))[tid] = ((const uint2*)g_iup)[tid];
    {   // stage U tile (40960B = 2560 uint4)
        const uint4* s = (const uint4*)g_Ubf;
        uint4* d = (uint4*)(sm + SM_R2);
        #pragma unroll
        for (int i = 0; i < 10; ++i) d[tid + i * 256] = s[tid + i * 256];
    }
    __syncthreads();

    // ---- gather Z -> bf16 Zbf[128][520] + zn partials ----
    {
        int r = tid >> 1, hh = tid & 1;
        int g = gid[r];
        const float4* zr = (const float4*)(Z_all + (size_t)(g < 0 ? 0 : g) * D) + hh * 64;
        char* zrow = sm + SM_R1 + r * Z_STRIDE + hh * 512;
        float acc = 0.f;
        #pragma unroll 4
        for (int i = 0; i < 64; ++i) {
            float4 z = make_float4(0.f, 0.f, 0.f, 0.f);
            if (g >= 0) z = zr[i];
            int d0 = hh * 256 + i * 4;
            float a0 = z.x - zmus[d0], a1 = z.y - zmus[d0 + 1];
            float a2 = z.z - zmus[d0 + 2], a3 = z.w - zmus[d0 + 3];
            acc = fmaf(a0, a0, fmaf(a1, a1, fmaf(a2, a2, fmaf(a3, a3, acc))));
            __nv_bfloat162 p0 = __floats2bfloat162_rn(z.x, z.y);
            __nv_bfloat162 p1 = __floats2bfloat162_rn(z.z, z.w);
            *(uint32_t*)(zrow + i * 8)     = *(uint32_t*)&p0;
            *(uint32_t*)(zrow + i * 8 + 4) = *(uint32_t*)&p1;
        }
        pbuf[tid] = acc;
    }
    __syncthreads();

    // ---- ZU = Z @ U via bf16 mma: warp w owns rows w*16..w*16+15 ----
    {
        float zu[4][4];
        #pragma unroll
        for (int i = 0; i < 4; ++i)
            #pragma unroll
            for (int j = 0; j < 4; ++j) zu[i][j] = 0.f;

        uint32_t zbase = smb + SM_R1 + (uint32_t)(wid * 16 + (lid & 15)) * Z_STRIDE;
        uint32_t ubase = smb + SM_R2 +
                         (uint32_t)((lid & 7) + 8 * ((lid >> 3) & 1)) * U_STRIDE +
                         (uint32_t)(8 * (lid >> 4)) * 2;
        uint32_t kh = (uint32_t)(8 * (lid >> 4)) * 2;
        #pragma unroll 4
        for (int ks = 0; ks < 32; ++ks) {
            uint32_t a[4], b0[4], b1[4];
            ldsm4(a, zbase + (uint32_t)(ks * 32) + kh);
            ldsm4t(b0, ubase + (uint32_t)(ks * 16) * U_STRIDE);
            ldsm4t(b1, ubase + (uint32_t)(ks * 16) * U_STRIDE + 32);
            mma16816(zu[0], a, b0);
            mma16816(zu[1], a, b0 + 2);
            mma16816(zu[2], a, b1);
            mma16816(zu[3], a, b1 + 2);
        }
        int r0 = wid * 16 + (lid >> 2);
        int c0 = (lid & 3) * 2;
        #pragma unroll
        for (int nt = 0; nt < 4; ++nt) {
            int c = nt * 8 + c0;
            coords[r0 * 33 + c]           = zu[nt][0] - g_xcU[c];
            coords[r0 * 33 + c + 1]       = zu[nt][1] - g_xcU[c + 1];
            coords[(r0 + 8) * 33 + c]     = zu[nt][2] - g_xcU[c];
            coords[(r0 + 8) * 33 + c + 1] = zu[nt][3] - g_xcU[c + 1];
        }
    }
    __syncthreads();

    // ---- secant (threads 0..127) ----
    if (tid < MROWS) {
        const float* cr = coords + tid * 33;
        float un = 0.f;
        #pragma unroll
        for (int j = 0; j < KK; ++j) {
            float v = cr[j] + g_dU[j];
            un = fmaf(v, v, un);
        }
        float zn = pbuf[2 * tid] + pbuf[2 * tid + 1];
        float C = zn - un;
        float E = __expf(-0.01f * un);
        float x_m2 = C * 0.999f;
        float x_m1 = C;
        bool done = false;
        for (int it = 0; it < 100; ++it) {
            if (done) break;
            float t1 = 1.f - E * __expf(-0.01f * x_m1);
            float f1 = t1 * t1 * x_m1 - C;
            float t2 = 1.f - E * __expf(-0.01f * x_m2);
            float f2 = t2 * t2 * x_m2 - C;
            float fd = f1 - f2;
            if (fabsf(fd) < 1e-6f) fd = (fd >= 0.f) ? 1e-6f : -1e-6f;
            float x = x_m1 - f1 * (x_m1 - x_m2) / fd;
            float step = fabsf(x - x_m1);
            x_m2 = x_m1;
            x_m1 = x;
            done = (step < 1e-6f);
        }
        kern[tid] = __expf(-0.01f * (un + x_m1));
    }

    // ---- build H[128][576] fp8 (overwrites Zbf) + stage V pass0 chunk0 ----
    {
        int m = tid >> 1, hh = tid & 1;
        const float* cr = coords + m * 33;
        char* hrow = sm + SM_R1 + m * H_STRIDE;
        const unsigned short* lut = (const unsigned short*)(sm + SM_LUT);
        int p0 = hh * 288, p1 = p0 + 288;
        for (int p = p0; p < p1; p += 4) {
            uint32_t w = 0;
            if (p < PP) {
                uint2 lu = *(const uint2*)(lut + p);
                int a0 = lu.x & 255, b0 = (lu.x >> 8) & 255;
                int a1 = (lu.x >> 16) & 255, b1 = (lu.x >> 24) & 255;
                int a2 = lu.y & 255, b2 = (lu.y >> 8) & 255;
                int a3 = (lu.y >> 16) & 255, b3 = (lu.y >> 24) & 255;
                w = pack4_e4m3(cr[a0] * cr[b0], cr[a1] * cr[b1],
                               cr[a2] * cr[b2], cr[a3] * cr[b3]);
            }
            *(uint32_t*)(hrow + p) = w;
        }
        // stage chunk 0 of pass 0 into V buf0 (1280 uint4)
        const uint4* src = (const uint4*)g_V8;
        uint4* dst = (uint4*)(sm + SM_R2);
        #pragma unroll
        for (int i = 0; i < 5; ++i) dst[tid + i * 256] = src[tid + i * 256];
    }
    __syncthreads();

    // ---- main GEMM: H(128x576) fp8 @ V fp8 -> 2 passes of N=256 ----
    const int mg = (wid >> 2) * 64;
    const int ng = (wid & 3) * 64;
    const uint32_t hlane = smb + SM_R1 + (uint32_t)(mg + (lid & 15)) * H_STRIDE +
                           (uint32_t)((lid >> 4) * 16);
    const uint32_t vlane = (uint32_t)(ng + (lid & 7) + 8 * ((lid >> 4) & 1)) * V_STRIDE +
                           (uint32_t)(((lid >> 3) & 1) * 16);
    const float INV256 = 0.00390625f;

    for (int np = 0; np < 2; ++np) {
        if (np == 1) {   // stage chunk 0 of pass 1 into buf0
            const uint4* src = (const uint4*)(g_V8 + (size_t)NCHUNK * VCHUNK_BYTES);
            uint4* dst = (uint4*)(sm + SM_R2);
            #pragma unroll
            for (int i = 0; i < 5; ++i) dst[tid + i * 256] = src[tid + i * 256];
            __syncthreads();
        }
        float acc[4][8][4];
        #pragma unroll
        for (int i = 0; i < 4; ++i)
            #pragma unroll
            for (int j = 0; j < 8; ++j)
                #pragma unroll
                for (int q = 0; q < 4; ++q) acc[i][j][q] = 0.f;

        for (int c = 0; c < NCHUNK; ++c) {
            uint4 t4[5];
            const bool have = (c + 1 < NCHUNK);
            if (have) {
                const uint4* nsrc =
                    (const uint4*)(g_V8 + (size_t)(np * NCHUNK + c + 1) * VCHUNK_BYTES);
                #pragma unroll
                for (int i = 0; i < 5; ++i) t4[i] = nsrc[tid + i * 256];
            }
            // compute chunk c from buf[c&1]
            const uint32_t vb = smb + SM_R2 + (uint32_t)((c & 1) * VCHUNK_BYTES) + vlane;
            #pragma unroll
            for (int ks = 0; ks < 2; ++ks) {
                uint32_t a[4][4];
                uint32_t koff = (uint32_t)(c * KCH + ks * 32);
                #pragma unroll
                for (int mt = 0; mt < 4; ++mt)
                    ldsm4(a[mt], hlane + (uint32_t)(mt * 16) * H_STRIDE + koff);
                #pragma unroll
                for (int q = 0; q < 4; ++q) {
                    uint32_t bfrag[4];
                    ldsm4(bfrag, vb + (uint32_t)(q * 16) * V_STRIDE + (uint32_t)(ks * 32));
                    #pragma unroll
                    for (int mt = 0; mt < 4; ++mt) {
                        mma8(acc[mt][2 * q],     a[mt], bfrag[0], bfrag[1]);
                        mma8(acc[mt][2 * q + 1], a[mt], bfrag[2], bfrag[3]);
                    }
                }
            }
            if (have) {
                uint4* dst = (uint4*)(sm + SM_R2 + ((c + 1) & 1) * VCHUNK_BYTES);
                #pragma unroll
                for (int i = 0; i < 5; ++i) dst[tid + i * 256] = t4[i];
            }
            __syncthreads();
        }

        // ---- epilogue for this n-half ----
        {
            int r0 = mg + (lid >> 2);
            int c0 = np * 256 + ng + (lid & 3) * 2;
            #pragma unroll
            for (int mt = 0; mt < 4; ++mt) {
                int rA = r0 + mt * 16, rB = rA + 8;
                int gA = gid[rA], gB = gid[rB];
                float kA = kern[rA], kB = kern[rB];
                #pragma unroll
                for (int nt = 0; nt < 8; ++nt) {
                    int col = c0 + nt * 8;
                    float ca = chg[col], cb = chg[col + 1];
                    if (gA >= 0) {
                        float2 z = *(const float2*)(Z_all + (size_t)gA * D + col);
                        float2 o;
                        o.x = z.x + kA * (ca + acc[mt][nt][0] * INV256);
                        o.y = z.y + kA * (cb + acc[mt][nt][1] * INV256);
                        *(float2*)(out + (size_t)gA * D + col) = o;
                    }
                    if (gB >= 0) {
                        float2 z = *(const float2*)(Z_all + (size_t)gB * D + col);
                        float2 o;
                        o.x = z.x + kB * (ca + acc[mt][nt][2] * INV256);
                        o.y = z.y + kB * (cb + acc[mt][nt][3] * INV256);
                        *(float2*)(out + (size_t)gB * D + col) = o;
                    }
                }
            }
        }
    }
}

// ===================== launch ================================
extern "C" void kernel_launch(void* const* d_in, const int* in_sizes, int n_in,
                              void* d_out, int out_size) {
    const float* Z_all  = (const float*)d_in[0];
    const float* U      = (const float*)d_in[1];
    const float* V      = (const float*)d_in[2];
    const float* zmu    = (const float*)d_in[3];
    const float* xc     = (const float*)d_in[4];
    const int*   choice = (const int*)  d_in[5];
    float*       out    = (float*)d_out;
    const int Nc = in_sizes[5];

    if ((size_t)Nc * D != (size_t)in_sizes[0]) {
        cudaMemcpyAsync(d_out, Z_all, (size_t)in_sizes[0] * sizeof(float),
                        cudaMemcpyDeviceToDevice, 0);
    }

    prep_kernel<<<369, 256>>>(U, V, zmu, xc);

    cudaFuncSetAttribute(glayer_main,
                         cudaFuncAttributeMaxDynamicSharedMemorySize, SM_TOTAL);
    int nblocks = (Nc + MROWS - 1) / MROWS;
    glayer_main<<<nblocks, NTHREADS, SM_TOTAL>>>(Z_all, zmu, choice, out, Nc);
}